// round 1
// baseline (speedup 1.0000x reference)
#include <cuda_runtime.h>
#include <cmath>

#define C_DIM   512
#define NTOK    4096          // H*W per batch
#define BATCH   4
#define M_TOT   (BATCH*NTOK)  // 16384
#define GROUPS  32
#define CG      (C_DIM/GROUPS) // 16

// ---------------- scratch (static device globals; no allocation) ----------------
__device__ float g_hn[(size_t)M_TOT*C_DIM];   // groupnorm output
__device__ float g_q [(size_t)M_TOT*C_DIM];
__device__ float g_k [(size_t)M_TOT*C_DIM];
__device__ float g_v [(size_t)M_TOT*C_DIM];
__device__ float g_o [(size_t)M_TOT*C_DIM];   // attention output
__device__ float g_s [(size_t)NTOK*NTOK];     // scores/probs, one batch at a time
__device__ float g_mean[BATCH*GROUPS];
__device__ float g_rstd[BATCH*GROUPS];

// ---------------- GroupNorm statistics: one block per (batch, group) ----------------
__global__ void gn_stats_kernel(const float* __restrict__ x) {
    int bg = blockIdx.x;                 // 0..127
    int b  = bg / GROUPS, g = bg % GROUPS;
    const float* base = x + (size_t)b*NTOK*C_DIM + g*CG;
    float s = 0.f, s2 = 0.f;
    // NTOK rows x CG floats = NTOK*(CG/4) float4
    for (int i = threadIdx.x; i < NTOK*(CG/4); i += blockDim.x) {
        int n = i >> 2, q4 = i & 3;
        float4 v = *(const float4*)(base + (size_t)n*C_DIM + q4*4);
        s  += v.x + v.y + v.z + v.w;
        s2 += v.x*v.x + v.y*v.y + v.z*v.z + v.w*v.w;
    }
    __shared__ float sh[256], sh2[256];
    sh[threadIdx.x] = s; sh2[threadIdx.x] = s2;
    __syncthreads();
    for (int off = 128; off > 0; off >>= 1) {
        if (threadIdx.x < off) {
            sh [threadIdx.x] += sh [threadIdx.x + off];
            sh2[threadIdx.x] += sh2[threadIdx.x + off];
        }
        __syncthreads();
    }
    if (threadIdx.x == 0) {
        float inv = 1.0f / (float)(NTOK * CG);
        float m   = sh[0] * inv;
        float var = sh2[0] * inv - m * m;
        g_mean[bg] = m;
        g_rstd[bg] = rsqrtf(var + 1e-6f);
    }
}

// ---------------- GroupNorm apply: hn = (x-mean)*rstd*scale + bias ----------------
__global__ void gn_apply_kernel(const float* __restrict__ x,
                                const float* __restrict__ scale,
                                const float* __restrict__ bias) {
    int idx = blockIdx.x * blockDim.x + threadIdx.x;     // float4 index
    if (idx >= M_TOT * (C_DIM/4)) return;
    int c4  = idx % (C_DIM/4);
    int row = idx / (C_DIM/4);
    int b   = row / NTOK;
    int c   = c4 * 4;
    int g   = c / CG;
    float m = g_mean[b*GROUPS + g];
    float r = g_rstd[b*GROUPS + g];
    float4 xv = *(const float4*)(x + (size_t)idx*4);
    float4 sv = *(const float4*)(scale + c);
    float4 bv = *(const float4*)(bias  + c);
    float4 o;
    o.x = (xv.x - m) * r * sv.x + bv.x;
    o.y = (xv.y - m) * r * sv.y + bv.y;
    o.z = (xv.z - m) * r * sv.z + bv.z;
    o.w = (xv.w - m) * r * sv.w + bv.w;
    *(float4*)(g_hn + (size_t)idx*4) = o;
}

// ---------------- Generic fp32 SGEMM: C = alpha*(A@B[^T]) + bias + resid ----------------
// BTRANS=false : B is [K,N] row-major (ldb = N stride)
// BTRANS=true  : B is [N,K] row-major (C = A @ B^T)
template<bool BTRANS>
__global__ __launch_bounds__(256) void sgemm_kernel(
    const float* __restrict__ A, const float* __restrict__ B, float* __restrict__ Cc,
    int M, int N, int K, int lda, int ldb, int ldc,
    float alpha, const float* __restrict__ bias, const float* __restrict__ resid)
{
    const int BM = 128, BN = 128, BK = 16;
    __shared__ float As[BK][BM];
    __shared__ float Bs[BK][BN];

    int tid = threadIdx.x;
    int bm  = blockIdx.y * BM;
    int bn  = blockIdx.x * BN;
    int tCol = tid % 16;        // 16 columns of threads
    int tRow = tid / 16;        // 16 rows of threads

    float acc[8][8];
    #pragma unroll
    for (int i = 0; i < 8; i++)
        #pragma unroll
        for (int j = 0; j < 8; j++) acc[i][j] = 0.f;

    // load-index decomposition
    int aRow = tid / 4;             // 0..63
    int aCol = (tid % 4) * 4;       // 0,4,8,12
    int bRow = tid / 32;            // 0..7   (normal-B path)
    int bCol = (tid % 32) * 4;      // 0..124

    for (int k0 = 0; k0 < K; k0 += BK) {
        // --- A tile [BM x BK], stored transposed As[k][m] ---
        #pragma unroll
        for (int i = 0; i < 2; i++) {
            int m = aRow + 64 * i;
            float4 v = *(const float4*)(A + (size_t)(bm + m) * lda + k0 + aCol);
            As[aCol + 0][m] = v.x;
            As[aCol + 1][m] = v.y;
            As[aCol + 2][m] = v.z;
            As[aCol + 3][m] = v.w;
        }
        // --- B tile ---
        if (BTRANS) {
            #pragma unroll
            for (int i = 0; i < 2; i++) {
                int n = aRow + 64 * i;
                float4 v = *(const float4*)(B + (size_t)(bn + n) * ldb + k0 + aCol);
                Bs[aCol + 0][n] = v.x;
                Bs[aCol + 1][n] = v.y;
                Bs[aCol + 2][n] = v.z;
                Bs[aCol + 3][n] = v.w;
            }
        } else {
            #pragma unroll
            for (int i = 0; i < 2; i++) {
                int kk = bRow + 8 * i;
                float4 v = *(const float4*)(B + (size_t)(k0 + kk) * ldb + bn + bCol);
                *(float4*)&Bs[kk][bCol] = v;
            }
        }
        __syncthreads();

        #pragma unroll
        for (int kk = 0; kk < BK; kk++) {
            float a[8], bb[8];
            *(float4*)(a)     = *(float4*)&As[kk][tRow * 8];
            *(float4*)(a + 4) = *(float4*)&As[kk][tRow * 8 + 4];
            *(float4*)(bb)     = *(float4*)&Bs[kk][tCol * 8];
            *(float4*)(bb + 4) = *(float4*)&Bs[kk][tCol * 8 + 4];
            #pragma unroll
            for (int i = 0; i < 8; i++)
                #pragma unroll
                for (int j = 0; j < 8; j++)
                    acc[i][j] += a[i] * bb[j];
        }
        __syncthreads();
    }

    // epilogue
    #pragma unroll
    for (int i = 0; i < 8; i++) {
        int row = bm + tRow * 8 + i;
        #pragma unroll
        for (int j = 0; j < 8; j += 4) {
            int col = bn + tCol * 8 + j;
            float4 o;
            o.x = acc[i][j + 0] * alpha;
            o.y = acc[i][j + 1] * alpha;
            o.z = acc[i][j + 2] * alpha;
            o.w = acc[i][j + 3] * alpha;
            if (bias) {
                float4 bv = *(const float4*)(bias + col);
                o.x += bv.x; o.y += bv.y; o.z += bv.z; o.w += bv.w;
            }
            if (resid) {
                float4 rv = *(const float4*)(resid + (size_t)row * ldc + col);
                o.x += rv.x; o.y += rv.y; o.z += rv.z; o.w += rv.w;
            }
            *(float4*)(Cc + (size_t)row * ldc + col) = o;
        }
    }
}

// ---------------- row softmax over 4096 columns: one block per row ----------------
__global__ void softmax_kernel(float* __restrict__ S) {
    int row = blockIdx.x;
    float* p = S + (size_t)row * NTOK;
    int tid  = threadIdx.x;
    int lane = tid & 31, warp = tid >> 5;

    float vals[16];
    float mx = -1e30f;
    #pragma unroll
    for (int i = 0; i < 16; i++) {
        vals[i] = p[tid + i * 256];
        mx = fmaxf(mx, vals[i]);
    }
    #pragma unroll
    for (int off = 16; off > 0; off >>= 1)
        mx = fmaxf(mx, __shfl_xor_sync(0xffffffffu, mx, off));

    __shared__ float sh[8];
    if (lane == 0) sh[warp] = mx;
    __syncthreads();
    float m = sh[0];
    #pragma unroll
    for (int w = 1; w < 8; w++) m = fmaxf(m, sh[w]);
    __syncthreads();

    float s = 0.f;
    #pragma unroll
    for (int i = 0; i < 16; i++) {
        vals[i] = expf(vals[i] - m);
        s += vals[i];
    }
    #pragma unroll
    for (int off = 16; off > 0; off >>= 1)
        s += __shfl_xor_sync(0xffffffffu, s, off);
    if (lane == 0) sh[warp] = s;
    __syncthreads();
    float tot = 0.f;
    #pragma unroll
    for (int w = 0; w < 8; w++) tot += sh[w];
    float inv = 1.0f / tot;

    #pragma unroll
    for (int i = 0; i < 16; i++)
        p[tid + i * 256] = vals[i] * inv;
}

// ---------------- launch ----------------
extern "C" void kernel_launch(void* const* d_in, const int* in_sizes, int n_in,
                              void* d_out, int out_size) {
    const float* x   = (const float*)d_in[0];
    const float* gns = (const float*)d_in[1];
    const float* gnb = (const float*)d_in[2];
    const float* wq  = (const float*)d_in[3];
    const float* bq  = (const float*)d_in[4];
    const float* wk  = (const float*)d_in[5];
    const float* bk  = (const float*)d_in[6];
    const float* wv  = (const float*)d_in[7];
    const float* bv  = (const float*)d_in[8];
    const float* wo  = (const float*)d_in[9];
    const float* bo  = (const float*)d_in[10];
    float* out = (float*)d_out;

    float *hn, *q, *k, *v, *o, *s;
    cudaGetSymbolAddress((void**)&hn, g_hn);
    cudaGetSymbolAddress((void**)&q,  g_q);
    cudaGetSymbolAddress((void**)&k,  g_k);
    cudaGetSymbolAddress((void**)&v,  g_v);
    cudaGetSymbolAddress((void**)&o,  g_o);
    cudaGetSymbolAddress((void**)&s,  g_s);

    gn_stats_kernel<<<BATCH*GROUPS, 256>>>(x);
    gn_apply_kernel<<<(M_TOT*(C_DIM/4) + 255)/256, 256>>>(x, gns, gnb);

    dim3 blk(256);
    dim3 gProj(C_DIM/128, M_TOT/128);   // (4, 128)
    sgemm_kernel<false><<<gProj, blk>>>(hn, wq, q, M_TOT, C_DIM, C_DIM,
                                        C_DIM, C_DIM, C_DIM, 1.f, bq, nullptr);
    sgemm_kernel<false><<<gProj, blk>>>(hn, wk, k, M_TOT, C_DIM, C_DIM,
                                        C_DIM, C_DIM, C_DIM, 1.f, bk, nullptr);
    sgemm_kernel<false><<<gProj, blk>>>(hn, wv, v, M_TOT, C_DIM, C_DIM,
                                        C_DIM, C_DIM, C_DIM, 1.f, bv, nullptr);

    float alpha = 1.0f / sqrtf((float)C_DIM);
    for (int b = 0; b < BATCH; b++) {
        const float* qb = q + (size_t)b * NTOK * C_DIM;
        const float* kb = k + (size_t)b * NTOK * C_DIM;
        const float* vb = v + (size_t)b * NTOK * C_DIM;
        float*       ob = o + (size_t)b * NTOK * C_DIM;

        dim3 gS(NTOK/128, NTOK/128);    // (32, 32)
        sgemm_kernel<true><<<gS, blk>>>(qb, kb, s, NTOK, NTOK, C_DIM,
                                        C_DIM, C_DIM, NTOK, alpha, nullptr, nullptr);
        softmax_kernel<<<NTOK, 256>>>(s);
        dim3 gO(C_DIM/128, NTOK/128);   // (4, 32)
        sgemm_kernel<false><<<gO, blk>>>(s, vb, ob, NTOK, C_DIM, NTOK,
                                         NTOK, C_DIM, C_DIM, 1.f, nullptr, nullptr);
    }

    sgemm_kernel<false><<<gProj, blk>>>(o, wo, out, M_TOT, C_DIM, C_DIM,
                                        C_DIM, C_DIM, C_DIM, 1.f, bo, x);
}

// round 2
// speedup vs baseline: 6.5354x; 6.5354x over previous
#include <cuda_runtime.h>
#include <cuda_bf16.h>
#include <cmath>
#include <cstdint>

#define C_DIM   512
#define NTOK    4096
#define BATCH   4
#define M_TOT   (BATCH*NTOK)   // 16384
#define GROUPS  32
#define CG      (C_DIM/GROUPS) // 16

typedef __nv_bfloat16 bf16;

// ---------------- scratch ----------------
__device__ bf16  g_hn[(size_t)M_TOT*C_DIM];
__device__ bf16  g_q [(size_t)M_TOT*C_DIM];
__device__ bf16  g_k [(size_t)M_TOT*C_DIM];
__device__ bf16  g_kt[(size_t)M_TOT*C_DIM];     // per-batch [C][NTOK]
__device__ bf16  g_v [(size_t)M_TOT*C_DIM];
__device__ bf16  g_o [(size_t)M_TOT*C_DIM];
__device__ bf16  g_wq[C_DIM*C_DIM];
__device__ bf16  g_wk[C_DIM*C_DIM];
__device__ bf16  g_wv[C_DIM*C_DIM];
__device__ bf16  g_wo[C_DIM*C_DIM];
__device__ float g_S [(size_t)BATCH*NTOK*NTOK]; // fp32 scores
__device__ bf16  g_P [(size_t)BATCH*NTOK*NTOK]; // bf16 probs
__device__ float g_mean[BATCH*GROUPS];
__device__ float g_rstd[BATCH*GROUPS];

// ---------------- helpers ----------------
__device__ __forceinline__ uint32_t smem_u32(const void* p) {
    return (uint32_t)__cvta_generic_to_shared(p);
}
__device__ __forceinline__ void cp_async16(uint32_t dst, const void* src) {
    asm volatile("cp.async.cg.shared.global [%0], [%1], 16;\n" :: "r"(dst), "l"(src));
}
__device__ __forceinline__ void cp_commit() {
    asm volatile("cp.async.commit_group;\n");
}
template<int N>
__device__ __forceinline__ void cp_wait() {
    asm volatile("cp.async.wait_group %0;\n" :: "n"(N));
}
__device__ __forceinline__ void ldsm4(uint32_t& r0, uint32_t& r1, uint32_t& r2, uint32_t& r3, uint32_t a) {
    asm volatile("ldmatrix.sync.aligned.m8n8.x4.shared.b16 {%0,%1,%2,%3}, [%4];\n"
        : "=r"(r0), "=r"(r1), "=r"(r2), "=r"(r3) : "r"(a));
}
__device__ __forceinline__ void ldsm4t(uint32_t& r0, uint32_t& r1, uint32_t& r2, uint32_t& r3, uint32_t a) {
    asm volatile("ldmatrix.sync.aligned.m8n8.x4.trans.shared.b16 {%0,%1,%2,%3}, [%4];\n"
        : "=r"(r0), "=r"(r1), "=r"(r2), "=r"(r3) : "r"(a));
}
__device__ __forceinline__ void mma16816(float* d, const uint32_t* a, const uint32_t* b) {
    asm volatile(
        "mma.sync.aligned.m16n8k16.row.col.f32.bf16.bf16.f32 "
        "{%0,%1,%2,%3}, {%4,%5,%6,%7}, {%8,%9}, {%0,%1,%2,%3};\n"
        : "+f"(d[0]), "+f"(d[1]), "+f"(d[2]), "+f"(d[3])
        : "r"(a[0]), "r"(a[1]), "r"(a[2]), "r"(a[3]), "r"(b[0]), "r"(b[1]));
}

// ---------------- GroupNorm stats ----------------
__global__ void gn_stats_kernel(const float* __restrict__ x) {
    int bg = blockIdx.x;
    int b = bg / GROUPS, g = bg % GROUPS;
    const float* base = x + (size_t)b*NTOK*C_DIM + g*CG;
    float s = 0.f, s2 = 0.f;
    for (int i = threadIdx.x; i < NTOK*(CG/4); i += blockDim.x) {
        int n = i >> 2, q4 = i & 3;
        float4 v = *(const float4*)(base + (size_t)n*C_DIM + q4*4);
        s  += v.x + v.y + v.z + v.w;
        s2 += v.x*v.x + v.y*v.y + v.z*v.z + v.w*v.w;
    }
    __shared__ float sh[256], sh2[256];
    sh[threadIdx.x] = s; sh2[threadIdx.x] = s2;
    __syncthreads();
    for (int off = 128; off > 0; off >>= 1) {
        if (threadIdx.x < off) {
            sh [threadIdx.x] += sh [threadIdx.x + off];
            sh2[threadIdx.x] += sh2[threadIdx.x + off];
        }
        __syncthreads();
    }
    if (threadIdx.x == 0) {
        float inv = 1.0f / (float)(NTOK * CG);
        float m   = sh[0] * inv;
        float var = sh2[0] * inv - m * m;
        g_mean[bg] = m;
        g_rstd[bg] = rsqrtf(var + 1e-6f);
    }
}

// ---------------- GroupNorm apply -> bf16 ----------------
__global__ void gn_apply_kernel(const float* __restrict__ x,
                                const float* __restrict__ scale,
                                const float* __restrict__ bias) {
    int idx = blockIdx.x * blockDim.x + threadIdx.x;   // float4 index
    if (idx >= M_TOT * (C_DIM/4)) return;
    int c4  = idx % (C_DIM/4);
    int row = idx / (C_DIM/4);
    int b   = row / NTOK;
    int c   = c4 * 4;
    int g   = c / CG;
    float m = g_mean[b*GROUPS + g];
    float r = g_rstd[b*GROUPS + g];
    float4 xv = *(const float4*)(x + (size_t)idx*4);
    float4 sv = *(const float4*)(scale + c);
    float4 bv = *(const float4*)(bias  + c);
    float o0 = (xv.x - m) * r * sv.x + bv.x;
    float o1 = (xv.y - m) * r * sv.y + bv.y;
    float o2 = (xv.z - m) * r * sv.z + bv.z;
    float o3 = (xv.w - m) * r * sv.w + bv.w;
    __nv_bfloat162* out = (__nv_bfloat162*)(g_hn + (size_t)idx*4);
    out[0] = __floats2bfloat162_rn(o0, o1);
    out[1] = __floats2bfloat162_rn(o2, o3);
}

// ---------------- fp32 -> bf16 convert ----------------
__global__ void f2bf_kernel(const float* __restrict__ s, bf16* __restrict__ d, int n4) {
    int i = blockIdx.x * blockDim.x + threadIdx.x;
    if (i >= n4) return;
    float4 v = *(const float4*)(s + (size_t)i*4);
    __nv_bfloat162* out = (__nv_bfloat162*)(d + (size_t)i*4);
    out[0] = __floats2bfloat162_rn(v.x, v.y);
    out[1] = __floats2bfloat162_rn(v.z, v.w);
}

// ---------------- bf16 transpose (per batch NTOKxC -> CxNTOK) ----------------
__global__ void transpose_kernel(const bf16* __restrict__ src, bf16* __restrict__ dst) {
    __shared__ bf16 t[32][33];
    int b = blockIdx.z;
    int n0 = blockIdx.x * 32, c0 = blockIdx.y * 32;
    const bf16* s = src + (size_t)b*NTOK*C_DIM;
    bf16*       d = dst + (size_t)b*NTOK*C_DIM;
    int x = threadIdx.x, y = threadIdx.y;   // 32 x 8
    #pragma unroll
    for (int i = 0; i < 32; i += 8)
        t[y+i][x] = s[(size_t)(n0+y+i)*C_DIM + c0 + x];
    __syncthreads();
    #pragma unroll
    for (int i = 0; i < 32; i += 8)
        d[(size_t)(c0+y+i)*NTOK + n0 + x] = t[x][y+i];
}

// ---------------- bf16 tensor-core GEMM: C = alpha*(A@B) (+bias) (+resid) ----------------
// A [M,K] row-major bf16, B [K,N] row-major bf16. Per-z offsets sA,sB,sC.
#define BM 128
#define BN 128
#define BK 32

template<bool OUT_BF16, bool BIAS, bool RESID>
__global__ __launch_bounds__(256, 2) void mma_gemm(
    const bf16* __restrict__ Ag, const bf16* __restrict__ Bg, void* __restrict__ Cg,
    int M, int N, int K, float alpha,
    const float* __restrict__ bias, const float* __restrict__ resid,
    size_t sA, size_t sB, size_t sC)
{
    __shared__ bf16 As[2][BM][BK+8];
    __shared__ bf16 Bs[2][BK][BN+8];

    const bf16* A = Ag + (size_t)blockIdx.z * sA;
    const bf16* B = Bg + (size_t)blockIdx.z * sB;

    int tid = threadIdx.x, lane = tid & 31, w = tid >> 5;
    int bm = blockIdx.y * BM, bn = blockIdx.x * BN;
    int warpM = (w & 1) * 64, warpN = (w >> 1) * 32;

    int arow = tid >> 2;          // 0..63
    int acol = (tid & 3) * 8;     // 0,8,16,24
    int brow = tid >> 4;          // 0..15
    int bcol = (tid & 15) * 8;    // 0..120

    const bf16* Abase = A + (size_t)bm * K;
    const bf16* Bbase = B + bn;

    float acc[4][4][4];
    #pragma unroll
    for (int mi = 0; mi < 4; mi++)
        #pragma unroll
        for (int ni = 0; ni < 4; ni++)
            #pragma unroll
            for (int t = 0; t < 4; t++) acc[mi][ni][t] = 0.f;

    int KT = K / BK;

    // prologue: tile 0 into buf 0
    {
        #pragma unroll
        for (int i = 0; i < 2; i++) {
            int r = arow + 64*i;
            cp_async16(smem_u32(&As[0][r][acol]), Abase + (size_t)r*K + acol);
        }
        #pragma unroll
        for (int i = 0; i < 2; i++) {
            int r = brow + 16*i;
            cp_async16(smem_u32(&Bs[0][r][bcol]), Bbase + (size_t)r*N + bcol);
        }
        cp_commit();
    }

    for (int kt = 0; kt < KT; kt++) {
        int buf = kt & 1;
        if (kt + 1 < KT) {
            int k0 = (kt + 1) * BK;
            int nb = buf ^ 1;
            #pragma unroll
            for (int i = 0; i < 2; i++) {
                int r = arow + 64*i;
                cp_async16(smem_u32(&As[nb][r][acol]), Abase + (size_t)r*K + k0 + acol);
            }
            #pragma unroll
            for (int i = 0; i < 2; i++) {
                int r = brow + 16*i;
                cp_async16(smem_u32(&Bs[nb][r][bcol]), Bbase + (size_t)(k0+r)*N + bcol);
            }
            cp_commit();
            cp_wait<1>();
        } else {
            cp_wait<0>();
        }
        __syncthreads();

        #pragma unroll
        for (int ks = 0; ks < 2; ks++) {
            int k16 = ks * 16;
            uint32_t aF[4][4], bF[4][2];
            #pragma unroll
            for (int mi = 0; mi < 4; mi++) {
                uint32_t addr = smem_u32(&As[buf][warpM + mi*16 + (lane & 15)][k16 + (lane >> 4)*8]);
                ldsm4(aF[mi][0], aF[mi][1], aF[mi][2], aF[mi][3], addr);
            }
            #pragma unroll
            for (int jj = 0; jj < 2; jj++) {
                uint32_t r0, r1, r2, r3;
                uint32_t addr = smem_u32(&Bs[buf][k16 + (lane & 15)][warpN + jj*16 + (lane >> 4)*8]);
                ldsm4t(r0, r1, r2, r3, addr);
                bF[jj*2  ][0] = r0; bF[jj*2  ][1] = r1;
                bF[jj*2+1][0] = r2; bF[jj*2+1][1] = r3;
            }
            #pragma unroll
            for (int mi = 0; mi < 4; mi++)
                #pragma unroll
                for (int ni = 0; ni < 4; ni++)
                    mma16816(acc[mi][ni], aF[mi], bF[ni]);
        }
        __syncthreads();
    }

    // epilogue
    int row0 = bm + warpM, col0 = bn + warpN;
    #pragma unroll
    for (int mi = 0; mi < 4; mi++) {
        #pragma unroll
        for (int ni = 0; ni < 4; ni++) {
            int r = row0 + mi*16 + (lane >> 2);
            int c = col0 + ni*8 + (lane & 3)*2;
            #pragma unroll
            for (int h = 0; h < 2; h++) {
                int rr = r + h*8;
                float v0 = acc[mi][ni][h*2+0] * alpha;
                float v1 = acc[mi][ni][h*2+1] * alpha;
                if (BIAS) { v0 += bias[c]; v1 += bias[c+1]; }
                if (RESID) {
                    const float* rp = resid + (size_t)rr*N + c;
                    v0 += rp[0]; v1 += rp[1];
                }
                if (OUT_BF16) {
                    bf16* C = (bf16*)Cg + (size_t)blockIdx.z * sC;
                    *(__nv_bfloat162*)(C + (size_t)rr*N + c) = __floats2bfloat162_rn(v0, v1);
                } else {
                    float* C = (float*)Cg + (size_t)blockIdx.z * sC;
                    *(float2*)(C + (size_t)rr*N + c) = make_float2(v0, v1);
                }
            }
        }
    }
}

// ---------------- softmax: fp32 scores -> bf16 probs ----------------
__global__ void softmax_kernel(const float* __restrict__ S, bf16* __restrict__ P) {
    size_t base = ((size_t)blockIdx.y * NTOK + blockIdx.x) * NTOK;
    const float* p = S + base;
    bf16*        o = P + base;
    int tid = threadIdx.x, lane = tid & 31, warp = tid >> 5;

    float vals[16];
    float mx = -1e30f;
    #pragma unroll
    for (int i = 0; i < 16; i++) {
        vals[i] = p[tid + i*256];
        mx = fmaxf(mx, vals[i]);
    }
    #pragma unroll
    for (int off = 16; off > 0; off >>= 1)
        mx = fmaxf(mx, __shfl_xor_sync(0xffffffffu, mx, off));
    __shared__ float sh[8];
    if (lane == 0) sh[warp] = mx;
    __syncthreads();
    float m = sh[0];
    #pragma unroll
    for (int wv = 1; wv < 8; wv++) m = fmaxf(m, sh[wv]);
    __syncthreads();

    float s = 0.f;
    #pragma unroll
    for (int i = 0; i < 16; i++) {
        vals[i] = expf(vals[i] - m);
        s += vals[i];
    }
    #pragma unroll
    for (int off = 16; off > 0; off >>= 1)
        s += __shfl_xor_sync(0xffffffffu, s, off);
    if (lane == 0) sh[warp] = s;
    __syncthreads();
    float tot = 0.f;
    #pragma unroll
    for (int wv = 0; wv < 8; wv++) tot += sh[wv];
    float inv = 1.0f / tot;

    #pragma unroll
    for (int i = 0; i < 16; i++)
        o[tid + i*256] = __float2bfloat16(vals[i] * inv);
}

// ---------------- launch ----------------
extern "C" void kernel_launch(void* const* d_in, const int* in_sizes, int n_in,
                              void* d_out, int out_size) {
    const float* x   = (const float*)d_in[0];
    const float* gns = (const float*)d_in[1];
    const float* gnb = (const float*)d_in[2];
    const float* wq  = (const float*)d_in[3];
    const float* bq  = (const float*)d_in[4];
    const float* wk  = (const float*)d_in[5];
    const float* bk  = (const float*)d_in[6];
    const float* wv  = (const float*)d_in[7];
    const float* bv  = (const float*)d_in[8];
    const float* wo  = (const float*)d_in[9];
    const float* bo  = (const float*)d_in[10];
    float* out = (float*)d_out;

    bf16 *hn, *q, *k, *kt, *v, *o, *P, *wqb, *wkb, *wvb, *wob;
    float *S;
    cudaGetSymbolAddress((void**)&hn,  g_hn);
    cudaGetSymbolAddress((void**)&q,   g_q);
    cudaGetSymbolAddress((void**)&k,   g_k);
    cudaGetSymbolAddress((void**)&kt,  g_kt);
    cudaGetSymbolAddress((void**)&v,   g_v);
    cudaGetSymbolAddress((void**)&o,   g_o);
    cudaGetSymbolAddress((void**)&P,   g_P);
    cudaGetSymbolAddress((void**)&S,   g_S);
    cudaGetSymbolAddress((void**)&wqb, g_wq);
    cudaGetSymbolAddress((void**)&wkb, g_wk);
    cudaGetSymbolAddress((void**)&wvb, g_wv);
    cudaGetSymbolAddress((void**)&wob, g_wo);

    gn_stats_kernel<<<BATCH*GROUPS, 256>>>(x);
    gn_apply_kernel<<<(M_TOT*(C_DIM/4) + 255)/256, 256>>>(x, gns, gnb);

    int wn4 = C_DIM*C_DIM/4;
    f2bf_kernel<<<(wn4+255)/256, 256>>>(wq, wqb, wn4);
    f2bf_kernel<<<(wn4+255)/256, 256>>>(wk, wkb, wn4);
    f2bf_kernel<<<(wn4+255)/256, 256>>>(wv, wvb, wn4);
    f2bf_kernel<<<(wn4+255)/256, 256>>>(wo, wob, wn4);

    dim3 blk(256);
    dim3 gProj(C_DIM/BN, M_TOT/BM, 1);   // (4, 128)
    mma_gemm<true, true, false><<<gProj, blk>>>(hn, wqb, q, M_TOT, C_DIM, C_DIM,
                                                1.f, bq, nullptr, 0, 0, 0);
    mma_gemm<true, true, false><<<gProj, blk>>>(hn, wkb, k, M_TOT, C_DIM, C_DIM,
                                                1.f, bk, nullptr, 0, 0, 0);
    mma_gemm<true, true, false><<<gProj, blk>>>(hn, wvb, v, M_TOT, C_DIM, C_DIM,
                                                1.f, bv, nullptr, 0, 0, 0);

    transpose_kernel<<<dim3(NTOK/32, C_DIM/32, BATCH), dim3(32, 8)>>>(k, kt);

    float alpha = 1.0f / sqrtf((float)C_DIM);
    size_t sQK = (size_t)NTOK * C_DIM;
    size_t sS  = (size_t)NTOK * NTOK;

    // scores: Q[b] @ kT[b]  -> fp32 S
    mma_gemm<false, false, false><<<dim3(NTOK/BN, NTOK/BM, BATCH), blk>>>(
        q, kt, S, NTOK, NTOK, C_DIM, alpha, nullptr, nullptr, sQK, sQK, sS);

    softmax_kernel<<<dim3(NTOK, BATCH), 256>>>(S, P);

    // PV: P[b] @ V[b] -> bf16 o
    mma_gemm<true, false, false><<<dim3(C_DIM/BN, NTOK/BM, BATCH), blk>>>(
        P, v, o, NTOK, C_DIM, NTOK, 1.f, nullptr, nullptr, sS, sQK, sQK);

    // final: o @ wo + bo + x -> fp32 out
    mma_gemm<false, true, true><<<gProj, blk>>>(o, wob, out, M_TOT, C_DIM, C_DIM,
                                                1.f, bo, x, 0, 0, 0);
}

// round 4
// speedup vs baseline: 7.1988x; 1.1015x over previous
#include <cuda_runtime.h>
#include <cuda_bf16.h>
#include <cmath>
#include <cstdint>

typedef __nv_bfloat16 bf16;

#define C_DIM   512
#define NTOK    4096
#define BATCH   4
#define M_TOT   (BATCH*NTOK)   // 16384
#define GROUPS  32
#define CG      (C_DIM/GROUPS) // 16

#define BM 128
#define BN 128
#define BK 32
#define NSTAGE 4

// ---------------- scratch ----------------
__device__ bf16  g_hn   [(size_t)M_TOT*C_DIM];
__device__ bf16  g_qkv  [(size_t)M_TOT*3*C_DIM];
__device__ bf16  g_o    [(size_t)M_TOT*C_DIM];
__device__ bf16  g_wqkvT[3*C_DIM*C_DIM];
__device__ bf16  g_woT  [C_DIM*C_DIM];
__device__ float g_bqkv [3*C_DIM];
__device__ bf16  g_E    [(size_t)BATCH*NTOK*NTOK];   // exp(scores) bf16
__device__ float g_psum [(size_t)BATCH*NTOK*32];     // per-tile row sums
__device__ float g_inv  [(size_t)BATCH*NTOK];        // 1/rowsum
__device__ float g_mean[BATCH*GROUPS];
__device__ float g_rstd[BATCH*GROUPS];

// ---------------- PTX helpers ----------------
__device__ __forceinline__ uint32_t smem_u32(const void* p) {
    return (uint32_t)__cvta_generic_to_shared(p);
}
__device__ __forceinline__ void cp_async16(uint32_t dst, const void* src) {
    asm volatile("cp.async.cg.shared.global [%0], [%1], 16;\n" :: "r"(dst), "l"(src));
}
__device__ __forceinline__ void cp_commit() { asm volatile("cp.async.commit_group;\n"); }
template<int N>
__device__ __forceinline__ void cp_wait() { asm volatile("cp.async.wait_group %0;\n" :: "n"(N)); }
__device__ __forceinline__ void ldsm4(uint32_t& r0, uint32_t& r1, uint32_t& r2, uint32_t& r3, uint32_t a) {
    asm volatile("ldmatrix.sync.aligned.m8n8.x4.shared.b16 {%0,%1,%2,%3}, [%4];\n"
        : "=r"(r0), "=r"(r1), "=r"(r2), "=r"(r3) : "r"(a));
}
__device__ __forceinline__ void ldsm4t(uint32_t& r0, uint32_t& r1, uint32_t& r2, uint32_t& r3, uint32_t a) {
    asm volatile("ldmatrix.sync.aligned.m8n8.x4.trans.shared.b16 {%0,%1,%2,%3}, [%4];\n"
        : "=r"(r0), "=r"(r1), "=r"(r2), "=r"(r3) : "r"(a));
}
__device__ __forceinline__ void mma16816(float* d, const uint32_t* a, const uint32_t* b) {
    asm volatile(
        "mma.sync.aligned.m16n8k16.row.col.f32.bf16.bf16.f32 "
        "{%0,%1,%2,%3}, {%4,%5,%6,%7}, {%8,%9}, {%0,%1,%2,%3};\n"
        : "+f"(d[0]), "+f"(d[1]), "+f"(d[2]), "+f"(d[3])
        : "r"(a[0]), "r"(a[1]), "r"(a[2]), "r"(a[3]), "r"(b[0]), "r"(b[1]));
}

// ---------------- GroupNorm stats ----------------
__global__ void gn_stats_kernel(const float* __restrict__ x) {
    int bg = blockIdx.x;
    int b = bg / GROUPS, g = bg % GROUPS;
    const float* base = x + (size_t)b*NTOK*C_DIM + g*CG;
    float s = 0.f, s2 = 0.f;
    for (int i = threadIdx.x; i < NTOK*(CG/4); i += blockDim.x) {
        int n = i >> 2, q4 = i & 3;
        float4 v = *(const float4*)(base + (size_t)n*C_DIM + q4*4);
        s  += v.x + v.y + v.z + v.w;
        s2 += v.x*v.x + v.y*v.y + v.z*v.z + v.w*v.w;
    }
    __shared__ float sh[256], sh2[256];
    sh[threadIdx.x] = s; sh2[threadIdx.x] = s2;
    __syncthreads();
    for (int off = 128; off > 0; off >>= 1) {
        if (threadIdx.x < off) {
            sh [threadIdx.x] += sh [threadIdx.x + off];
            sh2[threadIdx.x] += sh2[threadIdx.x + off];
        }
        __syncthreads();
    }
    if (threadIdx.x == 0) {
        float inv = 1.0f / (float)(NTOK * CG);
        float m   = sh[0] * inv;
        float var = sh2[0] * inv - m * m;
        g_mean[bg] = m;
        g_rstd[bg] = rsqrtf(var + 1e-6f);
    }
}

// ---------------- GroupNorm apply -> bf16 ----------------
__global__ void gn_apply_kernel(const float* __restrict__ x,
                                const float* __restrict__ scale,
                                const float* __restrict__ bias) {
    int idx = blockIdx.x * blockDim.x + threadIdx.x;
    if (idx >= M_TOT * (C_DIM/4)) return;
    int c4  = idx % (C_DIM/4);
    int row = idx / (C_DIM/4);
    int b   = row / NTOK;
    int c   = c4 * 4;
    int g   = c / CG;
    float m = g_mean[b*GROUPS + g];
    float r = g_rstd[b*GROUPS + g];
    float4 xv = *(const float4*)(x + (size_t)idx*4);
    float4 sv = *(const float4*)(scale + c);
    float4 bv = *(const float4*)(bias  + c);
    float o0 = (xv.x - m) * r * sv.x + bv.x;
    float o1 = (xv.y - m) * r * sv.y + bv.y;
    float o2 = (xv.z - m) * r * sv.z + bv.z;
    float o3 = (xv.w - m) * r * sv.w + bv.w;
    __nv_bfloat162* out = (__nv_bfloat162*)(g_hn + (size_t)idx*4);
    out[0] = __floats2bfloat162_rn(o0, o1);
    out[1] = __floats2bfloat162_rn(o2, o3);
}

// ---------------- weight transpose + convert: w[K][N] fp32 -> wT[N][K] bf16 ----------------
__global__ void wconv_t(const float* __restrict__ w, bf16* __restrict__ wt) {
    __shared__ float t[32][33];
    int k0 = blockIdx.x*32, n0 = blockIdx.y*32;
    int x = threadIdx.x, y = threadIdx.y;
    #pragma unroll
    for (int i = 0; i < 32; i += 8)
        t[y+i][x] = w[(size_t)(k0+y+i)*C_DIM + n0 + x];
    __syncthreads();
    #pragma unroll
    for (int i = 0; i < 32; i += 8)
        wt[(size_t)(n0+y+i)*C_DIM + k0 + x] = __float2bfloat16(t[x][y+i]);
}

__global__ void bias_cat(const float* a, const float* b, const float* c, float* o) {
    int t = blockIdx.x*256 + threadIdx.x;
    if (t < C_DIM) { o[t] = a[t]; o[C_DIM+t] = b[t]; o[2*C_DIM+t] = c[t]; }
}

// ---------------- rowsum -> inverse ----------------
__global__ void rowsum_inv(const float* __restrict__ psum, float* __restrict__ inv) {
    int i = blockIdx.x*256 + threadIdx.x;
    if (i >= BATCH*NTOK) return;
    const float* p = psum + (size_t)i*32;
    float s = 0.f;
    #pragma unroll
    for (int j = 0; j < 32; j++) s += p[j];
    inv[i] = 1.0f / s;
}

// ---------------- HMMA GEMM ----------------
// C = alpha*(A@B') [+bias] [+resid]; optional EXPE (write exp, emit rowsums),
// optional RSCALE (scale rows by inv).
// BLAY=0: B stored [N,K] row-major (ldb = K-dim stride). BLAY=1: B stored [K,N].
template<int BLAY, bool OUT_BF16, bool BIAS, bool RESID, bool EXPE, bool RSCALE>
__global__ __launch_bounds__(256, 2) void tc_gemm(
    const bf16* __restrict__ Ag, const bf16* __restrict__ Bg, void* __restrict__ Cg,
    int lda, int ldb, int ldc, int K, float alpha,
    const float* __restrict__ bias, const float* __restrict__ resid,
    float* __restrict__ psum, const float* __restrict__ inv,
    size_t sA, size_t sB, size_t sC)
{
    constexpr int APITCH = BK + 8;                       // 40
    constexpr int BPITCH = (BLAY == 0) ? (BK + 8) : (BN + 8);
    constexpr int BROWS  = (BLAY == 0) ? BN : BK;
    extern __shared__ char sm[];
    bf16*  As  = (bf16*)sm;                                   // [NSTAGE][BM][APITCH]
    bf16*  Bst = (bf16*)(sm + NSTAGE*BM*APITCH*2);            // [NSTAGE][BROWS][BPITCH]
    float* red = (float*)(sm + NSTAGE*(BM*APITCH + BROWS*BPITCH)*2);

    int tid = threadIdx.x, lane = tid & 31, w = tid >> 5;
    int bm = blockIdx.y * BM, bn = blockIdx.x * BN;
    int warpM = (w & 1) * 64, warpN = (w >> 1) * 32;
    int z = blockIdx.z;

    const bf16* A = Ag + (size_t)z * sA;
    const bf16* B = Bg + (size_t)z * sB;
    const bf16* Abase = A + (size_t)bm * lda;
    const bf16* Bbase = (BLAY == 0) ? (B + (size_t)bn * ldb) : (B + bn);

    float acc[4][4][4];
    #pragma unroll
    for (int mi = 0; mi < 4; mi++)
        #pragma unroll
        for (int ni = 0; ni < 4; ni++)
            #pragma unroll
            for (int t = 0; t < 4; t++) acc[mi][ni][t] = 0.f;

    auto load_tile = [&](int kt) {
        int s = kt & (NSTAGE-1);
        int k0 = kt * BK;
        bf16* Asm = As + s*BM*APITCH;
        bf16* Bsm = Bst + s*BROWS*BPITCH;
        #pragma unroll
        for (int j = 0; j < 2; j++) {
            int id = tid + j*256;
            int r = id >> 2, c = (id & 3) * 8;
            cp_async16(smem_u32(Asm + r*APITCH + c), Abase + (size_t)r*lda + k0 + c);
        }
        if (BLAY == 0) {
            #pragma unroll
            for (int j = 0; j < 2; j++) {
                int id = tid + j*256;
                int r = id >> 2, c = (id & 3) * 8;
                cp_async16(smem_u32(Bsm + r*BPITCH + c), Bbase + (size_t)r*ldb + k0 + c);
            }
        } else {
            #pragma unroll
            for (int j = 0; j < 2; j++) {
                int id = tid + j*256;
                int r = id >> 4, c = (id & 15) * 8;
                cp_async16(smem_u32(Bsm + r*BPITCH + c), Bbase + (size_t)(k0+r)*ldb + c);
            }
        }
    };

    int KT = K / BK;

    #pragma unroll
    for (int kt = 0; kt < NSTAGE-1; kt++) { load_tile(kt); cp_commit(); }

    for (int kt = 0; kt < KT; kt++) {
        cp_wait<NSTAGE-2>();
        __syncthreads();
        int s = kt & (NSTAGE-1);
        bf16* Asm = As + s*BM*APITCH;
        bf16* Bsm = Bst + s*BROWS*BPITCH;
        #pragma unroll
        for (int ks = 0; ks < 2; ks++) {
            int k16 = ks * 16;
            uint32_t aF[4][4], bF[4][2];
            #pragma unroll
            for (int mi = 0; mi < 4; mi++) {
                uint32_t addr = smem_u32(Asm + (warpM + mi*16 + (lane & 15))*APITCH
                                             + k16 + (lane >> 4)*8);
                ldsm4(aF[mi][0], aF[mi][1], aF[mi][2], aF[mi][3], addr);
            }
            #pragma unroll
            for (int jj = 0; jj < 2; jj++) {
                uint32_t r0, r1, r2, r3;
                if (BLAY == 0) {
                    uint32_t addr = smem_u32(Bsm + (warpN + jj*16 + (lane & 15))*BPITCH
                                                 + k16 + (lane >> 4)*8);
                    ldsm4(r0, r1, r2, r3, addr);
                    bF[jj*2  ][0] = r0; bF[jj*2  ][1] = r2;
                    bF[jj*2+1][0] = r1; bF[jj*2+1][1] = r3;
                } else {
                    uint32_t addr = smem_u32(Bsm + (k16 + (lane & 15))*BPITCH
                                                 + warpN + jj*16 + (lane >> 4)*8);
                    ldsm4t(r0, r1, r2, r3, addr);
                    bF[jj*2  ][0] = r0; bF[jj*2  ][1] = r1;
                    bF[jj*2+1][0] = r2; bF[jj*2+1][1] = r3;
                }
            }
            #pragma unroll
            for (int mi = 0; mi < 4; mi++)
                #pragma unroll
                for (int ni = 0; ni < 4; ni++)
                    mma16816(acc[mi][ni], aF[mi], bF[ni]);
        }
        if (kt + NSTAGE-1 < KT) load_tile(kt + NSTAGE-1);
        cp_commit();
    }

    // ---------------- epilogue ----------------
    int row0 = bm + warpM, col0 = bn + warpN;
    float rs[4][2];
    if (EXPE) {
        #pragma unroll
        for (int mi = 0; mi < 4; mi++) { rs[mi][0] = 0.f; rs[mi][1] = 0.f; }
    }
    #pragma unroll
    for (int mi = 0; mi < 4; mi++) {
        #pragma unroll
        for (int h = 0; h < 2; h++) {
            int rr = row0 + mi*16 + (lane >> 2) + h*8;
            float rowscale = 1.f;
            if (RSCALE) rowscale = inv[(size_t)z*NTOK + rr];
            #pragma unroll
            for (int ni = 0; ni < 4; ni++) {
                int c = col0 + ni*8 + (lane & 3)*2;
                float v0 = acc[mi][ni][h*2+0] * alpha;
                float v1 = acc[mi][ni][h*2+1] * alpha;
                if (EXPE) {
                    v0 = __expf(v0); v1 = __expf(v1);
                }
                if (BIAS)  { v0 += bias[c]; v1 += bias[c+1]; }
                if (RSCALE){ v0 *= rowscale; v1 *= rowscale; }
                if (RESID) {
                    const float* rp = resid + (size_t)rr*ldc + c;
                    v0 += rp[0]; v1 += rp[1];
                }
                if (OUT_BF16) {
                    bf16* C = (bf16*)Cg + (size_t)z * sC;
                    __nv_bfloat162 pk = __floats2bfloat162_rn(v0, v1);
                    *(__nv_bfloat162*)(C + (size_t)rr*ldc + c) = pk;
                    if (EXPE) {
                        rs[mi][h] += __bfloat162float(pk.x) + __bfloat162float(pk.y);
                    }
                } else {
                    float* C = (float*)Cg + (size_t)z * sC;
                    *(float2*)(C + (size_t)rr*ldc + c) = make_float2(v0, v1);
                }
            }
        }
    }
    if (EXPE) {
        #pragma unroll
        for (int mi = 0; mi < 4; mi++)
            #pragma unroll
            for (int h = 0; h < 2; h++) {
                float v = rs[mi][h];
                v += __shfl_xor_sync(0xffffffffu, v, 1);
                v += __shfl_xor_sync(0xffffffffu, v, 2);
                if ((lane & 3) == 0) {
                    int row_local = warpM + mi*16 + h*8 + (lane >> 2);
                    red[row_local*4 + (w >> 1)] = v;
                }
            }
        __syncthreads();
        if (tid < BM) {
            float s = red[tid*4+0] + red[tid*4+1] + red[tid*4+2] + red[tid*4+3];
            psum[((size_t)z*NTOK + bm + tid)*32 + blockIdx.x] = s;
        }
    }
}

// smem sizes (must match kernel)
#define SMEM0 (NSTAGE*(BM*(BK+8) + BN*(BK+8))*2 + BM*4*4)   // BLAY=0
#define SMEM1 (NSTAGE*(BM*(BK+8) + BK*(BN+8))*2 + BM*4*4)   // BLAY=1

// ---------------- launch ----------------
extern "C" void kernel_launch(void* const* d_in, const int* in_sizes, int n_in,
                              void* d_out, int out_size) {
    const float* x   = (const float*)d_in[0];
    const float* gns = (const float*)d_in[1];
    const float* gnb = (const float*)d_in[2];
    const float* wq  = (const float*)d_in[3];
    const float* bq  = (const float*)d_in[4];
    const float* wk  = (const float*)d_in[5];
    const float* bk  = (const float*)d_in[6];
    const float* wv  = (const float*)d_in[7];
    const float* bv  = (const float*)d_in[8];
    const float* wo  = (const float*)d_in[9];
    const float* bo  = (const float*)d_in[10];
    float* out = (float*)d_out;

    bf16 *hn, *qkv, *o, *E, *wqkvT, *woT;
    float *bqkv, *psum, *inv;
    cudaGetSymbolAddress((void**)&hn,    g_hn);
    cudaGetSymbolAddress((void**)&qkv,   g_qkv);
    cudaGetSymbolAddress((void**)&o,     g_o);
    cudaGetSymbolAddress((void**)&E,     g_E);
    cudaGetSymbolAddress((void**)&wqkvT, g_wqkvT);
    cudaGetSymbolAddress((void**)&woT,   g_woT);
    cudaGetSymbolAddress((void**)&bqkv,  g_bqkv);
    cudaGetSymbolAddress((void**)&psum,  g_psum);
    cudaGetSymbolAddress((void**)&inv,   g_inv);

    cudaFuncSetAttribute(tc_gemm<0,true,true,false,false,false>,
                         cudaFuncAttributeMaxDynamicSharedMemorySize, SMEM0);
    cudaFuncSetAttribute(tc_gemm<0,true,false,false,true,false>,
                         cudaFuncAttributeMaxDynamicSharedMemorySize, SMEM0);
    cudaFuncSetAttribute(tc_gemm<1,true,false,false,false,true>,
                         cudaFuncAttributeMaxDynamicSharedMemorySize, SMEM1);
    cudaFuncSetAttribute(tc_gemm<0,false,true,true,false,false>,
                         cudaFuncAttributeMaxDynamicSharedMemorySize, SMEM0);

    gn_stats_kernel<<<BATCH*GROUPS, 256>>>(x);
    gn_apply_kernel<<<(M_TOT*(C_DIM/4) + 255)/256, 256>>>(x, gns, gnb);

    dim3 wtb(32, 8), wtg(16, 16);
    wconv_t<<<wtg, wtb>>>(wq, wqkvT);
    wconv_t<<<wtg, wtb>>>(wk, wqkvT + C_DIM*C_DIM);
    wconv_t<<<wtg, wtb>>>(wv, wqkvT + 2*C_DIM*C_DIM);
    wconv_t<<<wtg, wtb>>>(wo, woT);
    bias_cat<<<2, 256>>>(bq, bk, bv, bqkv);

    // fused qkv projection: hn[16384,512] @ wqkvT'[512,1536] -> qkv bf16 [16384,1536]
    tc_gemm<0,true,true,false,false,false><<<dim3(3*C_DIM/BN, M_TOT/BM, 1), 256, SMEM0>>>(
        hn, wqkvT, qkv, C_DIM, C_DIM, 3*C_DIM, C_DIM, 1.f,
        bqkv, nullptr, nullptr, nullptr, 0, 0, 0);

    float alpha = 1.0f / sqrtf((float)C_DIM);
    size_t sRow = (size_t)NTOK * (3*C_DIM);
    size_t sS   = (size_t)NTOK * NTOK;

    // E = exp(alpha * q @ k^T), bf16, + per-tile rowsums
    tc_gemm<0,true,false,false,true,false><<<dim3(NTOK/BN, NTOK/BM, BATCH), 256, SMEM0>>>(
        qkv, qkv + C_DIM, E, 3*C_DIM, 3*C_DIM, NTOK, C_DIM, alpha,
        nullptr, nullptr, psum, nullptr, sRow, sRow, sS);

    rowsum_inv<<<(BATCH*NTOK + 255)/256, 256>>>(psum, inv);

    // o = diag(inv) * (E @ V)   (V in-place inside qkv, [K,N] layout)
    tc_gemm<1,true,false,false,false,true><<<dim3(C_DIM/BN, NTOK/BM, BATCH), 256, SMEM1>>>(
        E, qkv + 2*C_DIM, o, NTOK, 3*C_DIM, C_DIM, NTOK, 1.f,
        nullptr, nullptr, nullptr, inv, sS, sRow, (size_t)NTOK*C_DIM);

    // out = o @ woT' + bo + x  (fp32)
    tc_gemm<0,false,true,true,false,false><<<dim3(C_DIM/BN, M_TOT/BM, 1), 256, SMEM0>>>(
        o, woT, out, C_DIM, C_DIM, C_DIM, C_DIM, 1.f,
        bo, x, nullptr, nullptr, 0, 0, 0);
}

// round 6
// speedup vs baseline: 7.3600x; 1.0224x over previous
#include <cuda_runtime.h>
#include <cuda_bf16.h>
#include <cmath>
#include <cstdint>

typedef __nv_bfloat16 bf16;

#define C_DIM   512
#define NTOK    4096
#define BATCH   4
#define M_TOT   (BATCH*NTOK)   // 16384
#define GROUPS  32
#define CG      (C_DIM/GROUPS) // 16

#define BM 128
#define BN 128
#define BK 64
#define NSTAGE 3

// ---------------- scratch ----------------
__device__ bf16  g_hn   [(size_t)M_TOT*C_DIM];
__device__ bf16  g_qkv  [(size_t)M_TOT*3*C_DIM];
__device__ bf16  g_o    [(size_t)M_TOT*C_DIM];
__device__ bf16  g_wqkvT[3*C_DIM*C_DIM];
__device__ bf16  g_woT  [C_DIM*C_DIM];
__device__ float g_bqkv [3*C_DIM];
__device__ bf16  g_E    [(size_t)BATCH*NTOK*NTOK];   // exp(scores) bf16
__device__ float g_psum [(size_t)BATCH*NTOK*32];     // per-tile row sums
__device__ float g_inv  [(size_t)BATCH*NTOK];        // 1/rowsum
__device__ float g_mean[BATCH*GROUPS];
__device__ float g_rstd[BATCH*GROUPS];

// ---------------- PTX helpers ----------------
__device__ __forceinline__ uint32_t smem_u32(const void* p) {
    return (uint32_t)__cvta_generic_to_shared(p);
}
__device__ __forceinline__ void cp_async16(uint32_t dst, const void* src) {
    asm volatile("cp.async.cg.shared.global [%0], [%1], 16;\n" :: "r"(dst), "l"(src));
}
__device__ __forceinline__ void cp_commit() { asm volatile("cp.async.commit_group;\n"); }
template<int N>
__device__ __forceinline__ void cp_wait() { asm volatile("cp.async.wait_group %0;\n" :: "n"(N)); }
__device__ __forceinline__ void ldsm4(uint32_t& r0, uint32_t& r1, uint32_t& r2, uint32_t& r3, uint32_t a) {
    asm volatile("ldmatrix.sync.aligned.m8n8.x4.shared.b16 {%0,%1,%2,%3}, [%4];\n"
        : "=r"(r0), "=r"(r1), "=r"(r2), "=r"(r3) : "r"(a));
}
__device__ __forceinline__ void ldsm4t(uint32_t& r0, uint32_t& r1, uint32_t& r2, uint32_t& r3, uint32_t a) {
    asm volatile("ldmatrix.sync.aligned.m8n8.x4.trans.shared.b16 {%0,%1,%2,%3}, [%4];\n"
        : "=r"(r0), "=r"(r1), "=r"(r2), "=r"(r3) : "r"(a));
}
__device__ __forceinline__ void mma16816(float* d, const uint32_t* a, const uint32_t* b) {
    asm volatile(
        "mma.sync.aligned.m16n8k16.row.col.f32.bf16.bf16.f32 "
        "{%0,%1,%2,%3}, {%4,%5,%6,%7}, {%8,%9}, {%0,%1,%2,%3};\n"
        : "+f"(d[0]), "+f"(d[1]), "+f"(d[2]), "+f"(d[3])
        : "r"(a[0]), "r"(a[1]), "r"(a[2]), "r"(a[3]), "r"(b[0]), "r"(b[1]));
}

// ---------------- GroupNorm stats ----------------
__global__ void gn_stats_kernel(const float* __restrict__ x) {
    int bg = blockIdx.x;
    int b = bg / GROUPS, g = bg % GROUPS;
    const float* base = x + (size_t)b*NTOK*C_DIM + g*CG;
    float s = 0.f, s2 = 0.f;
    for (int i = threadIdx.x; i < NTOK*(CG/4); i += blockDim.x) {
        int n = i >> 2, q4 = i & 3;
        float4 v = *(const float4*)(base + (size_t)n*C_DIM + q4*4);
        s  += v.x + v.y + v.z + v.w;
        s2 += v.x*v.x + v.y*v.y + v.z*v.z + v.w*v.w;
    }
    __shared__ float sh[256], sh2[256];
    sh[threadIdx.x] = s; sh2[threadIdx.x] = s2;
    __syncthreads();
    for (int off = 128; off > 0; off >>= 1) {
        if (threadIdx.x < off) {
            sh [threadIdx.x] += sh [threadIdx.x + off];
            sh2[threadIdx.x] += sh2[threadIdx.x + off];
        }
        __syncthreads();
    }
    if (threadIdx.x == 0) {
        float inv = 1.0f / (float)(NTOK * CG);
        float m   = sh[0] * inv;
        float var = sh2[0] * inv - m * m;
        g_mean[bg] = m;
        g_rstd[bg] = rsqrtf(var + 1e-6f);
    }
}

// ---------------- GroupNorm apply -> bf16 ----------------
__global__ void gn_apply_kernel(const float* __restrict__ x,
                                const float* __restrict__ scale,
                                const float* __restrict__ bias) {
    int idx = blockIdx.x * blockDim.x + threadIdx.x;
    if (idx >= M_TOT * (C_DIM/4)) return;
    int c4  = idx % (C_DIM/4);
    int row = idx / (C_DIM/4);
    int b   = row / NTOK;
    int c   = c4 * 4;
    int g   = c / CG;
    float m = g_mean[b*GROUPS + g];
    float r = g_rstd[b*GROUPS + g];
    float4 xv = *(const float4*)(x + (size_t)idx*4);
    float4 sv = *(const float4*)(scale + c);
    float4 bv = *(const float4*)(bias  + c);
    float o0 = (xv.x - m) * r * sv.x + bv.x;
    float o1 = (xv.y - m) * r * sv.y + bv.y;
    float o2 = (xv.z - m) * r * sv.z + bv.z;
    float o3 = (xv.w - m) * r * sv.w + bv.w;
    __nv_bfloat162* out = (__nv_bfloat162*)(g_hn + (size_t)idx*4);
    out[0] = __floats2bfloat162_rn(o0, o1);
    out[1] = __floats2bfloat162_rn(o2, o3);
}

// ---------------- fused weight prep: 4 transposes + bias concat (one launch) ----------------
// z = 0..2 : wq/wk/wv -> g_wqkvT sections ; z = 3 : wo -> g_woT
__global__ void wprep(const float* __restrict__ wq, const float* __restrict__ wk,
                      const float* __restrict__ wv, const float* __restrict__ wo,
                      const float* __restrict__ bq, const float* __restrict__ bk,
                      const float* __restrict__ bv,
                      bf16* __restrict__ wqkvT, bf16* __restrict__ woT,
                      float* __restrict__ bqkv) {
    __shared__ float t[32][33];
    int z = blockIdx.z;
    const float* w = (z == 0) ? wq : (z == 1) ? wk : (z == 2) ? wv : wo;
    bf16* wt = (z < 3) ? (wqkvT + (size_t)z*C_DIM*C_DIM) : woT;
    int k0 = blockIdx.x*32, n0 = blockIdx.y*32;
    int x = threadIdx.x, y = threadIdx.y;
    #pragma unroll
    for (int i = 0; i < 32; i += 8)
        t[y+i][x] = w[(size_t)(k0+y+i)*C_DIM + n0 + x];
    __syncthreads();
    #pragma unroll
    for (int i = 0; i < 32; i += 8)
        wt[(size_t)(n0+y+i)*C_DIM + k0 + x] = __float2bfloat16(t[x][y+i]);
    if (z == 0 && blockIdx.x == 0 && blockIdx.y == 0) {
        int tid = y*32 + x;
        #pragma unroll
        for (int i = 0; i < 2; i++) {
            int c = tid + i*256;
            bqkv[c] = bq[c]; bqkv[C_DIM+c] = bk[c]; bqkv[2*C_DIM+c] = bv[c];
        }
    }
}

// ---------------- rowsum -> inverse ----------------
__global__ void rowsum_inv(const float* __restrict__ psum, float* __restrict__ inv) {
    int i = blockIdx.x*256 + threadIdx.x;
    if (i >= BATCH*NTOK) return;
    const float* p = psum + (size_t)i*32;
    float s = 0.f;
    #pragma unroll
    for (int j = 0; j < 32; j++) s += p[j];
    inv[i] = 1.0f / s;
}

// ---------------- HMMA GEMM ----------------
// C = alpha*(A@B') [+bias] [+resid]; EXPE: write exp + rowsums; RSCALE: row scale by inv.
// BLAY=0: B stored [N,K] row-major. BLAY=1: B stored [K,N].
template<int BLAY, bool OUT_BF16, bool BIAS, bool RESID, bool EXPE, bool RSCALE>
__global__ __launch_bounds__(256, 2) void tc_gemm(
    const bf16* __restrict__ Ag, const bf16* __restrict__ Bg, void* __restrict__ Cg,
    int lda, int ldb, int ldc, int K, float alpha,
    const float* __restrict__ bias, const float* __restrict__ resid,
    float* __restrict__ psum, const float* __restrict__ inv,
    size_t sA, size_t sB, size_t sC)
{
    constexpr int APITCH = BK + 8;                       // 72
    constexpr int BPITCH = (BLAY == 0) ? (BK + 8) : (BN + 8);
    constexpr int BROWS  = (BLAY == 0) ? BN : BK;
    constexpr int ATILE  = BM * APITCH;
    constexpr int BTILE  = BROWS * BPITCH;
    extern __shared__ char sm[];
    bf16*  As  = (bf16*)sm;                              // [NSTAGE][BM][APITCH]
    bf16*  Bst = (bf16*)(sm + NSTAGE*ATILE*2);           // [NSTAGE][BROWS][BPITCH]
    float* red = (float*)(sm + NSTAGE*(ATILE + BTILE)*2);

    int tid = threadIdx.x, lane = tid & 31, w = tid >> 5;
    int bm = blockIdx.y * BM, bn = blockIdx.x * BN;
    int warpM = (w & 1) * 64, warpN = (w >> 1) * 32;
    int z = blockIdx.z;

    const bf16* A = Ag + (size_t)z * sA;
    const bf16* B = Bg + (size_t)z * sB;
    const bf16* Abase = A + (size_t)bm * lda;
    const bf16* Bbase = (BLAY == 0) ? (B + (size_t)bn * ldb) : (B + bn);

    float acc[4][4][4];
    #pragma unroll
    for (int mi = 0; mi < 4; mi++)
        #pragma unroll
        for (int ni = 0; ni < 4; ni++)
            #pragma unroll
            for (int t = 0; t < 4; t++) acc[mi][ni][t] = 0.f;

    auto load_tile = [&](int kt) {
        int s = kt % NSTAGE;
        int k0 = kt * BK;
        bf16* Asm = As + s*ATILE;
        bf16* Bsm = Bst + s*BTILE;
        // A: 128 rows x 64 cols -> 1024 16B chunks
        #pragma unroll
        for (int j = 0; j < 4; j++) {
            int id = tid + j*256;
            int r = id >> 3, c = (id & 7) * 8;
            cp_async16(smem_u32(Asm + r*APITCH + c), Abase + (size_t)r*lda + k0 + c);
        }
        if (BLAY == 0) {
            #pragma unroll
            for (int j = 0; j < 4; j++) {
                int id = tid + j*256;
                int r = id >> 3, c = (id & 7) * 8;
                cp_async16(smem_u32(Bsm + r*BPITCH + c), Bbase + (size_t)r*ldb + k0 + c);
            }
        } else {
            #pragma unroll
            for (int j = 0; j < 4; j++) {
                int id = tid + j*256;
                int r = id >> 4, c = (id & 15) * 8;
                cp_async16(smem_u32(Bsm + r*BPITCH + c), Bbase + (size_t)(k0+r)*ldb + c);
            }
        }
        cp_commit();
    };

    int KT = K / BK;
    load_tile(0);
    load_tile(1);

    for (int kt = 0; kt < KT; kt++) {
        if (kt + 1 < KT) cp_wait<1>(); else cp_wait<0>();
        __syncthreads();
        if (kt + 2 < KT) load_tile(kt + 2);   // overlaps with MMA below
        int s = kt % NSTAGE;
        bf16* Asm = As + s*ATILE;
        bf16* Bsm = Bst + s*BTILE;
        #pragma unroll
        for (int ks = 0; ks < 4; ks++) {
            int k16 = ks * 16;
            uint32_t aF[4][4], bF[4][2];
            #pragma unroll
            for (int mi = 0; mi < 4; mi++) {
                uint32_t addr = smem_u32(Asm + (warpM + mi*16 + (lane & 15))*APITCH
                                             + k16 + (lane >> 4)*8);
                ldsm4(aF[mi][0], aF[mi][1], aF[mi][2], aF[mi][3], addr);
            }
            #pragma unroll
            for (int jj = 0; jj < 2; jj++) {
                uint32_t r0, r1, r2, r3;
                if (BLAY == 0) {
                    uint32_t addr = smem_u32(Bsm + (warpN + jj*16 + (lane & 15))*BPITCH
                                                 + k16 + (lane >> 4)*8);
                    ldsm4(r0, r1, r2, r3, addr);
                    bF[jj*2  ][0] = r0; bF[jj*2  ][1] = r2;
                    bF[jj*2+1][0] = r1; bF[jj*2+1][1] = r3;
                } else {
                    uint32_t addr = smem_u32(Bsm + (k16 + (lane & 15))*BPITCH
                                                 + warpN + jj*16 + (lane >> 4)*8);
                    ldsm4t(r0, r1, r2, r3, addr);
                    bF[jj*2  ][0] = r0; bF[jj*2  ][1] = r1;
                    bF[jj*2+1][0] = r2; bF[jj*2+1][1] = r3;
                }
            }
            #pragma unroll
            for (int mi = 0; mi < 4; mi++)
                #pragma unroll
                for (int ni = 0; ni < 4; ni++)
                    mma16816(acc[mi][ni], aF[mi], bF[ni]);
        }
    }

    // ---------------- epilogue ----------------
    int row0 = bm + warpM, col0 = bn + warpN;
    float rs[4][2];
    if (EXPE) {
        #pragma unroll
        for (int mi = 0; mi < 4; mi++) { rs[mi][0] = 0.f; rs[mi][1] = 0.f; }
    }
    #pragma unroll
    for (int mi = 0; mi < 4; mi++) {
        #pragma unroll
        for (int h = 0; h < 2; h++) {
            int rr = row0 + mi*16 + (lane >> 2) + h*8;
            float rowscale = 1.f;
            if (RSCALE) rowscale = inv[(size_t)z*NTOK + rr];
            #pragma unroll
            for (int ni = 0; ni < 4; ni++) {
                int c = col0 + ni*8 + (lane & 3)*2;
                float v0 = acc[mi][ni][h*2+0] * alpha;
                float v1 = acc[mi][ni][h*2+1] * alpha;
                if (EXPE) { v0 = __expf(v0); v1 = __expf(v1); }
                if (BIAS)  { v0 += bias[c]; v1 += bias[c+1]; }
                if (RSCALE){ v0 *= rowscale; v1 *= rowscale; }
                if (RESID) {
                    const float* rp = resid + (size_t)rr*ldc + c;
                    v0 += rp[0]; v1 += rp[1];
                }
                if (OUT_BF16) {
                    bf16* C = (bf16*)Cg + (size_t)z * sC;
                    __nv_bfloat162 pk = __floats2bfloat162_rn(v0, v1);
                    *(__nv_bfloat162*)(C + (size_t)rr*ldc + c) = pk;
                    if (EXPE) rs[mi][h] += __bfloat162float(pk.x) + __bfloat162float(pk.y);
                } else {
                    float* C = (float*)Cg + (size_t)z * sC;
                    *(float2*)(C + (size_t)rr*ldc + c) = make_float2(v0, v1);
                }
            }
        }
    }
    if (EXPE) {
        #pragma unroll
        for (int mi = 0; mi < 4; mi++)
            #pragma unroll
            for (int h = 0; h < 2; h++) {
                float v = rs[mi][h];
                v += __shfl_xor_sync(0xffffffffu, v, 1);
                v += __shfl_xor_sync(0xffffffffu, v, 2);
                if ((lane & 3) == 0) {
                    int row_local = warpM + mi*16 + h*8 + (lane >> 2);
                    red[row_local*4 + (w >> 1)] = v;
                }
            }
        __syncthreads();
        if (tid < BM) {
            float s = red[tid*4+0] + red[tid*4+1] + red[tid*4+2] + red[tid*4+3];
            psum[((size_t)z*NTOK + bm + tid)*32 + blockIdx.x] = s;
        }
    }
}

// smem sizes
#define SMEM0 (NSTAGE*(BM*(BK+8) + BN*(BK+8))*2 + BM*4*4)   // BLAY=0: 112640
#define SMEM1 (NSTAGE*(BM*(BK+8) + BK*(BN+8))*2 + BM*4*4)   // BLAY=1: 109568

// ---------------- launch ----------------
extern "C" void kernel_launch(void* const* d_in, const int* in_sizes, int n_in,
                              void* d_out, int out_size) {
    const float* x   = (const float*)d_in[0];
    const float* gns = (const float*)d_in[1];
    const float* gnb = (const float*)d_in[2];
    const float* wq  = (const float*)d_in[3];
    const float* bq  = (const float*)d_in[4];
    const float* wk  = (const float*)d_in[5];
    const float* bk  = (const float*)d_in[6];
    const float* wv  = (const float*)d_in[7];
    const float* bv  = (const float*)d_in[8];
    const float* wo  = (const float*)d_in[9];
    const float* bo  = (const float*)d_in[10];
    float* out = (float*)d_out;

    bf16 *hn, *qkv, *o, *E, *wqkvT, *woT;
    float *bqkv, *psum, *inv;
    cudaGetSymbolAddress((void**)&hn,    g_hn);
    cudaGetSymbolAddress((void**)&qkv,   g_qkv);
    cudaGetSymbolAddress((void**)&o,     g_o);
    cudaGetSymbolAddress((void**)&E,     g_E);
    cudaGetSymbolAddress((void**)&wqkvT, g_wqkvT);
    cudaGetSymbolAddress((void**)&woT,   g_woT);
    cudaGetSymbolAddress((void**)&bqkv,  g_bqkv);
    cudaGetSymbolAddress((void**)&psum,  g_psum);
    cudaGetSymbolAddress((void**)&inv,   g_inv);

    cudaFuncSetAttribute(tc_gemm<0,true,true,false,false,false>,
                         cudaFuncAttributeMaxDynamicSharedMemorySize, SMEM0);
    cudaFuncSetAttribute(tc_gemm<0,true,false,false,true,false>,
                         cudaFuncAttributeMaxDynamicSharedMemorySize, SMEM0);
    cudaFuncSetAttribute(tc_gemm<1,true,false,false,false,true>,
                         cudaFuncAttributeMaxDynamicSharedMemorySize, SMEM1);
    cudaFuncSetAttribute(tc_gemm<0,false,true,true,false,false>,
                         cudaFuncAttributeMaxDynamicSharedMemorySize, SMEM0);

    // launch order chosen so ncu -s 5 profiles the scores GEMM
    gn_stats_kernel<<<BATCH*GROUPS, 256>>>(x);                                   // 1
    gn_apply_kernel<<<(M_TOT*(C_DIM/4) + 255)/256, 256>>>(x, gns, gnb);          // 2
    wprep<<<dim3(16, 16, 4), dim3(32, 8)>>>(wq, wk, wv, wo, bq, bk, bv,
                                            wqkvT, woT, bqkv);                   // 3

    // fused qkv projection: hn[16384,512] @ wqkvT'[512,1536] -> qkv bf16
    tc_gemm<0,true,true,false,false,false><<<dim3(3*C_DIM/BN, M_TOT/BM, 1), 256, SMEM0>>>(
        hn, wqkvT, qkv, C_DIM, C_DIM, 3*C_DIM, C_DIM, 1.f,
        bqkv, nullptr, nullptr, nullptr, 0, 0, 0);                               // 4

    float alpha = 1.0f / sqrtf((float)C_DIM);
    size_t sRow = (size_t)NTOK * (3*C_DIM);
    size_t sS   = (size_t)NTOK * NTOK;

    // E = exp(alpha * q @ k^T), bf16, + per-tile rowsums
    tc_gemm<0,true,false,false,true,false><<<dim3(NTOK/BN, NTOK/BM, BATCH), 256, SMEM0>>>(
        qkv, qkv + C_DIM, E, 3*C_DIM, 3*C_DIM, NTOK, C_DIM, alpha,
        nullptr, nullptr, psum, nullptr, sRow, sRow, sS);                        // 5 <- ncu

    rowsum_inv<<<(BATCH*NTOK + 255)/256, 256>>>(psum, inv);                      // 6

    // o = diag(inv) * (E @ V)   (V in-place inside qkv, [K,N] layout)
    tc_gemm<1,true,false,false,false,true><<<dim3(C_DIM/BN, NTOK/BM, BATCH), 256, SMEM1>>>(
        E, qkv + 2*C_DIM, o, NTOK, 3*C_DIM, C_DIM, NTOK, 1.f,
        nullptr, nullptr, nullptr, inv, sS, sRow, (size_t)NTOK*C_DIM);           // 7

    // out = o @ woT' + bo + x  (fp32)
    tc_gemm<0,false,true,true,false,false><<<dim3(C_DIM/BN, M_TOT/BM, 1), 256, SMEM0>>>(
        o, woT, out, C_DIM, C_DIM, C_DIM, C_DIM, 1.f,
        bo, x, nullptr, nullptr, 0, 0, 0);                                       // 8
}

// round 8
// speedup vs baseline: 7.5206x; 1.0218x over previous
#include <cuda_runtime.h>
#include <cuda_bf16.h>
#include <cmath>
#include <cstdint>

typedef __nv_bfloat16 bf16;

#define C_DIM   512
#define NTOK    4096
#define BATCH   4
#define M_TOT   (BATCH*NTOK)   // 16384
#define GROUPS  32
#define CG      (C_DIM/GROUPS) // 16

#define BM 128
#define BN 128
#define BK 64
#define NSTAGE 3

// ---------------- scratch ----------------
__device__ bf16  g_hn   [(size_t)M_TOT*C_DIM];
__device__ bf16  g_qkv  [(size_t)M_TOT*3*C_DIM];
__device__ bf16  g_o    [(size_t)M_TOT*C_DIM];
__device__ bf16  g_wqkvT[3*C_DIM*C_DIM];
__device__ bf16  g_woT  [C_DIM*C_DIM];
__device__ float g_bqkv [3*C_DIM];
__device__ bf16  g_E    [(size_t)BATCH*NTOK*NTOK];   // exp(scores) bf16
__device__ float g_psum [(size_t)BATCH*NTOK*32];     // per-tile row sums
__device__ float g_mean[BATCH*GROUPS];
__device__ float g_rstd[BATCH*GROUPS];

// ---------------- PTX helpers ----------------
__device__ __forceinline__ uint32_t smem_u32(const void* p) {
    return (uint32_t)__cvta_generic_to_shared(p);
}
__device__ __forceinline__ void cp_async16(uint32_t dst, const void* src) {
    asm volatile("cp.async.cg.shared.global [%0], [%1], 16;\n" :: "r"(dst), "l"(src));
}
__device__ __forceinline__ void cp_commit() { asm volatile("cp.async.commit_group;\n"); }
template<int N>
__device__ __forceinline__ void cp_wait() { asm volatile("cp.async.wait_group %0;\n" :: "n"(N)); }
__device__ __forceinline__ void ldsm4(uint32_t& r0, uint32_t& r1, uint32_t& r2, uint32_t& r3, uint32_t a) {
    asm volatile("ldmatrix.sync.aligned.m8n8.x4.shared.b16 {%0,%1,%2,%3}, [%4];\n"
        : "=r"(r0), "=r"(r1), "=r"(r2), "=r"(r3) : "r"(a));
}
__device__ __forceinline__ void ldsm4t(uint32_t& r0, uint32_t& r1, uint32_t& r2, uint32_t& r3, uint32_t a) {
    asm volatile("ldmatrix.sync.aligned.m8n8.x4.trans.shared.b16 {%0,%1,%2,%3}, [%4];\n"
        : "=r"(r0), "=r"(r1), "=r"(r2), "=r"(r3) : "r"(a));
}
__device__ __forceinline__ void mma16816(float* d, const uint32_t* a, const uint32_t* b) {
    asm volatile(
        "mma.sync.aligned.m16n8k16.row.col.f32.bf16.bf16.f32 "
        "{%0,%1,%2,%3}, {%4,%5,%6,%7}, {%8,%9}, {%0,%1,%2,%3};\n"
        : "+f"(d[0]), "+f"(d[1]), "+f"(d[2]), "+f"(d[3])
        : "r"(a[0]), "r"(a[1]), "r"(a[2]), "r"(a[3]), "r"(b[0]), "r"(b[1]));
}

// ---------------- GroupNorm stats ----------------
__global__ void gn_stats_kernel(const float* __restrict__ x) {
    int bg = blockIdx.x;
    int b = bg / GROUPS, g = bg % GROUPS;
    const float* base = x + (size_t)b*NTOK*C_DIM + g*CG;
    float s = 0.f, s2 = 0.f;
    for (int i = threadIdx.x; i < NTOK*(CG/4); i += blockDim.x) {
        int n = i >> 2, q4 = i & 3;
        float4 v = *(const float4*)(base + (size_t)n*C_DIM + q4*4);
        s  += v.x + v.y + v.z + v.w;
        s2 += v.x*v.x + v.y*v.y + v.z*v.z + v.w*v.w;
    }
    __shared__ float sh[256], sh2[256];
    sh[threadIdx.x] = s; sh2[threadIdx.x] = s2;
    __syncthreads();
    for (int off = 128; off > 0; off >>= 1) {
        if (threadIdx.x < off) {
            sh [threadIdx.x] += sh [threadIdx.x + off];
            sh2[threadIdx.x] += sh2[threadIdx.x + off];
        }
        __syncthreads();
    }
    if (threadIdx.x == 0) {
        float inv = 1.0f / (float)(NTOK * CG);
        float m   = sh[0] * inv;
        float var = sh2[0] * inv - m * m;
        g_mean[bg] = m;
        g_rstd[bg] = rsqrtf(var + 1e-6f);
    }
}

// ---------------- GroupNorm apply -> bf16 ----------------
__global__ void gn_apply_kernel(const float* __restrict__ x,
                                const float* __restrict__ scale,
                                const float* __restrict__ bias) {
    int idx = blockIdx.x * blockDim.x + threadIdx.x;
    if (idx >= M_TOT * (C_DIM/4)) return;
    int c4  = idx % (C_DIM/4);
    int row = idx / (C_DIM/4);
    int b   = row / NTOK;
    int c   = c4 * 4;
    int g   = c / CG;
    float m = g_mean[b*GROUPS + g];
    float r = g_rstd[b*GROUPS + g];
    float4 xv = *(const float4*)(x + (size_t)idx*4);
    float4 sv = *(const float4*)(scale + c);
    float4 bv = *(const float4*)(bias  + c);
    float o0 = (xv.x - m) * r * sv.x + bv.x;
    float o1 = (xv.y - m) * r * sv.y + bv.y;
    float o2 = (xv.z - m) * r * sv.z + bv.z;
    float o3 = (xv.w - m) * r * sv.w + bv.w;
    __nv_bfloat162* out = (__nv_bfloat162*)(g_hn + (size_t)idx*4);
    out[0] = __floats2bfloat162_rn(o0, o1);
    out[1] = __floats2bfloat162_rn(o2, o3);
}

// ---------------- fused weight prep: 4 transposes + bias concat ----------------
__global__ void wprep(const float* __restrict__ wq, const float* __restrict__ wk,
                      const float* __restrict__ wv, const float* __restrict__ wo,
                      const float* __restrict__ bq, const float* __restrict__ bk,
                      const float* __restrict__ bv,
                      bf16* __restrict__ wqkvT, bf16* __restrict__ woT,
                      float* __restrict__ bqkv) {
    __shared__ float t[32][33];
    int z = blockIdx.z;
    const float* w = (z == 0) ? wq : (z == 1) ? wk : (z == 2) ? wv : wo;
    bf16* wt = (z < 3) ? (wqkvT + (size_t)z*C_DIM*C_DIM) : woT;
    int k0 = blockIdx.x*32, n0 = blockIdx.y*32;
    int x = threadIdx.x, y = threadIdx.y;
    #pragma unroll
    for (int i = 0; i < 32; i += 8)
        t[y+i][x] = w[(size_t)(k0+y+i)*C_DIM + n0 + x];
    __syncthreads();
    #pragma unroll
    for (int i = 0; i < 32; i += 8)
        wt[(size_t)(n0+y+i)*C_DIM + k0 + x] = __float2bfloat16(t[x][y+i]);
    if (z == 0 && blockIdx.x == 0 && blockIdx.y == 0) {
        int tid = y*32 + x;
        #pragma unroll
        for (int i = 0; i < 2; i++) {
            int c = tid + i*256;
            bqkv[c] = bq[c]; bqkv[C_DIM+c] = bk[c]; bqkv[2*C_DIM+c] = bv[c];
        }
    }
}

// ---------------- HMMA GEMM ----------------
// C = alpha*(A@B') [+bias] [+resid]; EXPE: write exp + rowsums to psum;
// RSCALE: compute inv=1/rowsum from psum in prologue, scale rows at epilogue.
// BLAY=0: B stored [N,K] row-major. BLAY=1: B stored [K,N].
template<int BLAY, bool OUT_BF16, bool BIAS, bool RESID, bool EXPE, bool RSCALE>
__global__ __launch_bounds__(256, 2) void tc_gemm(
    const bf16* __restrict__ Ag, const bf16* __restrict__ Bg, void* __restrict__ Cg,
    int lda, int ldb, int ldc, int K, float alpha,
    const float* __restrict__ bias, const float* __restrict__ resid,
    float* __restrict__ psum,
    size_t sA, size_t sB, size_t sC)
{
    constexpr int APITCH = BK + 8;                       // 72
    constexpr int BPITCH = (BLAY == 0) ? (BK + 8) : (BN + 8);
    constexpr int BROWS  = (BLAY == 0) ? BN : BK;
    constexpr int ATILE  = BM * APITCH;
    constexpr int BTILE  = BROWS * BPITCH;
    extern __shared__ char sm[];
    bf16*  As  = (bf16*)sm;                              // [NSTAGE][BM][APITCH]
    bf16*  Bst = (bf16*)(sm + NSTAGE*ATILE*2);           // [NSTAGE][BROWS][BPITCH]
    float* red = (float*)(sm + NSTAGE*(ATILE + BTILE)*2);  // BM*4 floats / invS[BM]

    int tid = threadIdx.x, lane = tid & 31, w = tid >> 5;
    int bm = blockIdx.y * BM, bn = blockIdx.x * BN;
    int warpM = (w & 1) * 64, warpN = (w >> 1) * 32;
    int z = blockIdx.z;

    const bf16* A = Ag + (size_t)z * sA;
    const bf16* B = Bg + (size_t)z * sB;
    const bf16* Abase = A + (size_t)bm * lda;
    const bf16* Bbase = (BLAY == 0) ? (B + (size_t)bn * ldb) : (B + bn);

    // RSCALE prologue: per-CTA row-sum inverses into smem (covered by mainloop syncs)
    if (RSCALE) {
        if (tid < BM) {
            const float* p = psum + ((size_t)z*NTOK + bm + tid)*32;
            float s = 0.f;
            #pragma unroll
            for (int j = 0; j < 32; j++) s += p[j];
            red[tid] = 1.0f / s;
        }
    }

    float acc[4][4][4];
    #pragma unroll
    for (int mi = 0; mi < 4; mi++)
        #pragma unroll
        for (int ni = 0; ni < 4; ni++)
            #pragma unroll
            for (int t = 0; t < 4; t++) acc[mi][ni][t] = 0.f;

    auto load_tile = [&](int kt) {
        int s = kt % NSTAGE;
        int k0 = kt * BK;
        bf16* Asm = As + s*ATILE;
        bf16* Bsm = Bst + s*BTILE;
        #pragma unroll
        for (int j = 0; j < 4; j++) {
            int id = tid + j*256;
            int r = id >> 3, c = (id & 7) * 8;
            cp_async16(smem_u32(Asm + r*APITCH + c), Abase + (size_t)r*lda + k0 + c);
        }
        if (BLAY == 0) {
            #pragma unroll
            for (int j = 0; j < 4; j++) {
                int id = tid + j*256;
                int r = id >> 3, c = (id & 7) * 8;
                cp_async16(smem_u32(Bsm + r*BPITCH + c), Bbase + (size_t)r*ldb + k0 + c);
            }
        } else {
            #pragma unroll
            for (int j = 0; j < 4; j++) {
                int id = tid + j*256;
                int r = id >> 4, c = (id & 15) * 8;
                cp_async16(smem_u32(Bsm + r*BPITCH + c), Bbase + (size_t)(k0+r)*ldb + c);
            }
        }
        cp_commit();
    };

    int KT = K / BK;
    load_tile(0);
    load_tile(1);

    for (int kt = 0; kt < KT; kt++) {
        if (kt + 1 < KT) cp_wait<1>(); else cp_wait<0>();
        __syncthreads();
        int s = kt % NSTAGE;
        bf16* Asm = As + s*ATILE;
        bf16* Bsm = Bst + s*BTILE;
        #pragma unroll
        for (int ks = 0; ks < 4; ks++) {
            int k16 = ks * 16;
            uint32_t aF[4][4], bF[4][2];
            // fragments FIRST ...
            #pragma unroll
            for (int mi = 0; mi < 4; mi++) {
                uint32_t addr = smem_u32(Asm + (warpM + mi*16 + (lane & 15))*APITCH
                                             + k16 + (lane >> 4)*8);
                ldsm4(aF[mi][0], aF[mi][1], aF[mi][2], aF[mi][3], addr);
            }
            #pragma unroll
            for (int jj = 0; jj < 2; jj++) {
                uint32_t r0, r1, r2, r3;
                if (BLAY == 0) {
                    uint32_t addr = smem_u32(Bsm + (warpN + jj*16 + (lane & 15))*BPITCH
                                                 + k16 + (lane >> 4)*8);
                    ldsm4(r0, r1, r2, r3, addr);
                    bF[jj*2  ][0] = r0; bF[jj*2  ][1] = r2;
                    bF[jj*2+1][0] = r1; bF[jj*2+1][1] = r3;
                } else {
                    uint32_t addr = smem_u32(Bsm + (k16 + (lane & 15))*BPITCH
                                                 + warpN + jj*16 + (lane >> 4)*8);
                    ldsm4t(r0, r1, r2, r3, addr);
                    bF[jj*2  ][0] = r0; bF[jj*2  ][1] = r1;
                    bF[jj*2+1][0] = r2; bF[jj*2+1][1] = r3;
                }
            }
            // ... THEN issue next-tile loads (overlap with the MMAs below)
            if (ks == 0 && kt + 2 < KT) load_tile(kt + 2);
            #pragma unroll
            for (int mi = 0; mi < 4; mi++)
                #pragma unroll
                for (int ni = 0; ni < 4; ni++)
                    mma16816(acc[mi][ni], aF[mi], bF[ni]);
        }
    }

    // ---------------- epilogue ----------------
    int row0 = bm + warpM, col0 = bn + warpN;
    float rs[4][2];
    if (EXPE) {
        #pragma unroll
        for (int mi = 0; mi < 4; mi++) { rs[mi][0] = 0.f; rs[mi][1] = 0.f; }
    }
    #pragma unroll
    for (int mi = 0; mi < 4; mi++) {
        #pragma unroll
        for (int h = 0; h < 2; h++) {
            int rl = warpM + mi*16 + (lane >> 2) + h*8;   // row within CTA tile
            int rr = bm + rl;
            float rowscale = 1.f;
            if (RSCALE) rowscale = red[rl];
            #pragma unroll
            for (int ni = 0; ni < 4; ni++) {
                int c = col0 + ni*8 + (lane & 3)*2;
                float v0 = acc[mi][ni][h*2+0] * alpha;
                float v1 = acc[mi][ni][h*2+1] * alpha;
                if (EXPE) { v0 = __expf(v0); v1 = __expf(v1); }
                if (BIAS)  { v0 += bias[c]; v1 += bias[c+1]; }
                if (RSCALE){ v0 *= rowscale; v1 *= rowscale; }
                if (RESID) {
                    const float* rp = resid + (size_t)rr*ldc + c;
                    v0 += rp[0]; v1 += rp[1];
                }
                if (OUT_BF16) {
                    bf16* C = (bf16*)Cg + (size_t)z * sC;
                    __nv_bfloat162 pk = __floats2bfloat162_rn(v0, v1);
                    *(__nv_bfloat162*)(C + (size_t)rr*ldc + c) = pk;
                    if (EXPE) rs[mi][h] += __bfloat162float(pk.x) + __bfloat162float(pk.y);
                } else {
                    float* C = (float*)Cg + (size_t)z * sC;
                    *(float2*)(C + (size_t)rr*ldc + c) = make_float2(v0, v1);
                }
            }
        }
    }
    if (EXPE) {
        #pragma unroll
        for (int mi = 0; mi < 4; mi++)
            #pragma unroll
            for (int h = 0; h < 2; h++) {
                float v = rs[mi][h];
                v += __shfl_xor_sync(0xffffffffu, v, 1);
                v += __shfl_xor_sync(0xffffffffu, v, 2);
                if ((lane & 3) == 0) {
                    int row_local = warpM + mi*16 + h*8 + (lane >> 2);
                    red[row_local*4 + (w >> 1)] = v;
                }
            }
        __syncthreads();
        if (tid < BM) {
            float s = red[tid*4+0] + red[tid*4+1] + red[tid*4+2] + red[tid*4+3];
            psum[((size_t)z*NTOK + bm + tid)*32 + blockIdx.x] = s;
        }
    }
}

// smem sizes
#define SMEM0 (NSTAGE*(BM*(BK+8) + BN*(BK+8))*2 + BM*4*4)   // BLAY=0
#define SMEM1 (NSTAGE*(BM*(BK+8) + BK*(BN+8))*2 + BM*4*4)   // BLAY=1

// ---------------- launch ----------------
extern "C" void kernel_launch(void* const* d_in, const int* in_sizes, int n_in,
                              void* d_out, int out_size) {
    const float* x   = (const float*)d_in[0];
    const float* gns = (const float*)d_in[1];
    const float* gnb = (const float*)d_in[2];
    const float* wq  = (const float*)d_in[3];
    const float* bq  = (const float*)d_in[4];
    const float* wk  = (const float*)d_in[5];
    const float* bk  = (const float*)d_in[6];
    const float* wv  = (const float*)d_in[7];
    const float* bv  = (const float*)d_in[8];
    const float* wo  = (const float*)d_in[9];
    const float* bo  = (const float*)d_in[10];
    float* out = (float*)d_out;

    bf16 *hn, *qkv, *o, *E, *wqkvT, *woT;
    float *bqkv, *psum;
    cudaGetSymbolAddress((void**)&hn,    g_hn);
    cudaGetSymbolAddress((void**)&qkv,   g_qkv);
    cudaGetSymbolAddress((void**)&o,     g_o);
    cudaGetSymbolAddress((void**)&E,     g_E);
    cudaGetSymbolAddress((void**)&wqkvT, g_wqkvT);
    cudaGetSymbolAddress((void**)&woT,   g_woT);
    cudaGetSymbolAddress((void**)&bqkv,  g_bqkv);
    cudaGetSymbolAddress((void**)&psum,  g_psum);

    cudaFuncSetAttribute(tc_gemm<0,true,true,false,false,false>,
                         cudaFuncAttributeMaxDynamicSharedMemorySize, SMEM0);
    cudaFuncSetAttribute(tc_gemm<0,true,false,false,true,false>,
                         cudaFuncAttributeMaxDynamicSharedMemorySize, SMEM0);
    cudaFuncSetAttribute(tc_gemm<1,true,false,false,false,true>,
                         cudaFuncAttributeMaxDynamicSharedMemorySize, SMEM1);
    cudaFuncSetAttribute(tc_gemm<0,false,true,true,false,false>,
                         cudaFuncAttributeMaxDynamicSharedMemorySize, SMEM0);

    gn_stats_kernel<<<BATCH*GROUPS, 256>>>(x);                                   // 1
    gn_apply_kernel<<<(M_TOT*(C_DIM/4) + 255)/256, 256>>>(x, gns, gnb);          // 2
    wprep<<<dim3(16, 16, 4), dim3(32, 8)>>>(wq, wk, wv, wo, bq, bk, bv,
                                            wqkvT, woT, bqkv);                   // 3

    // fused qkv projection
    tc_gemm<0,true,true,false,false,false><<<dim3(3*C_DIM/BN, M_TOT/BM, 1), 256, SMEM0>>>(
        hn, wqkvT, qkv, C_DIM, C_DIM, 3*C_DIM, C_DIM, 1.f,
        bqkv, nullptr, nullptr, 0, 0, 0);                                        // 4

    float alpha = 1.0f / sqrtf((float)C_DIM);
    size_t sRow = (size_t)NTOK * (3*C_DIM);
    size_t sS   = (size_t)NTOK * NTOK;

    // E = exp(alpha * q @ k^T) + per-tile rowsums
    tc_gemm<0,true,false,false,true,false><<<dim3(NTOK/BN, NTOK/BM, BATCH), 256, SMEM0>>>(
        qkv, qkv + C_DIM, E, 3*C_DIM, 3*C_DIM, NTOK, C_DIM, alpha,
        nullptr, nullptr, psum, sRow, sRow, sS);                                 // 5 <- ncu

    // o = diag(1/rowsum) * (E @ V)   (inv computed in-kernel from psum)
    tc_gemm<1,true,false,false,false,true><<<dim3(C_DIM/BN, NTOK/BM, BATCH), 256, SMEM1>>>(
        E, qkv + 2*C_DIM, o, NTOK, 3*C_DIM, C_DIM, NTOK, 1.f,
        nullptr, nullptr, psum, sS, sRow, (size_t)NTOK*C_DIM);                   // 6

    // out = o @ woT' + bo + x  (fp32)
    tc_gemm<0,false,true,true,false,false><<<dim3(C_DIM/BN, M_TOT/BM, 1), 256, SMEM0>>>(
        o, woT, out, C_DIM, C_DIM, C_DIM, C_DIM, 1.f,
        bo, x, nullptr, 0, 0, 0);                                                // 7
}